// round 2
// baseline (speedup 1.0000x reference)
#include <cuda_runtime.h>
#include <math.h>

#define BB 2
#define NQ 2048
#define LL 2048
#define DM 1024
#define NH 16
#define HD 64

// Scratch (allocation-free rule: __device__ globals)
__device__ float g_Q[BB * NH * NQ * HD];   // [B,H,N,HD], pre-scaled by HD^-0.5
__device__ float g_K[BB * NH * LL * HD];   // [B,H,L,HD]
__device__ float g_V[BB * NH * LL * HD];   // [B,H,L,HD]
__device__ float g_Ao[BB * NQ * DM];       // attention output, [B,N,D]
__device__ int   g_mask_is_byte;           // 1 if pad_mask is stored as 1-byte bool

// Detect whether pad_mask arrived as int32 {0,1} or as 1-byte bool.
// Reads only the first 4096 bytes (valid under both layouts).
__global__ void detect_mask_kernel(const unsigned int* __restrict__ mask_words) {
    if (threadIdx.x == 0 && blockIdx.x == 0) {
        int flag = 0;
        for (int i = 0; i < 1024; i++) {
            if (mask_words[i] & ~1u) { flag = 1; break; }
        }
        g_mask_is_byte = flag;
    }
}

// Projection GEMM: Y = (X @ W + bias) * scale
// HEAD=true : Y stored as [B, H, S, HD]  (head h == blockIdx.x since tile=64=HD)
// HEAD=false: Y stored as [B*S, DM] flat
template <bool HEAD>
__global__ __launch_bounds__(256)
void proj_kernel(const float* __restrict__ X, const float* __restrict__ W,
                 const float* __restrict__ bias, float* __restrict__ Y,
                 int S, float scale)
{
    __shared__ float As[16][65];   // [k][m], padded
    __shared__ float Bs[16][64];   // [k][n], float4-aligned rows

    const int tid = threadIdx.x;
    const int tx = tid & 15;
    const int ty = tid >> 4;
    const int row0 = blockIdx.y * 64;
    const int col0 = blockIdx.x * 64;

    const int am = tid >> 2;           // 0..63
    const int ak = (tid & 3) << 2;     // 0,4,8,12
    const int bk = tid >> 4;           // 0..15
    const int bn = (tid & 15) << 2;    // 0..60

    const float* Xp = X + (size_t)(row0 + am) * DM + ak;
    const float* Wp = W + (size_t)bk * DM + col0 + bn;

    float acc[4][4];
#pragma unroll
    for (int i = 0; i < 4; i++)
#pragma unroll
        for (int j = 0; j < 4; j++) acc[i][j] = 0.0f;

    for (int k0 = 0; k0 < DM; k0 += 16) {
        float4 a4 = *(const float4*)(Xp + k0);
        float4 b4 = *(const float4*)(Wp + (size_t)k0 * DM);
        __syncthreads();
        As[ak + 0][am] = a4.x;
        As[ak + 1][am] = a4.y;
        As[ak + 2][am] = a4.z;
        As[ak + 3][am] = a4.w;
        *(float4*)&Bs[bk][bn] = b4;
        __syncthreads();
#pragma unroll
        for (int kk = 0; kk < 16; kk++) {
            float a0 = As[kk][ty * 4 + 0];
            float a1 = As[kk][ty * 4 + 1];
            float a2 = As[kk][ty * 4 + 2];
            float a3 = As[kk][ty * 4 + 3];
            float4 b = *(const float4*)&Bs[kk][tx * 4];
            acc[0][0] += a0 * b.x; acc[0][1] += a0 * b.y; acc[0][2] += a0 * b.z; acc[0][3] += a0 * b.w;
            acc[1][0] += a1 * b.x; acc[1][1] += a1 * b.y; acc[1][2] += a1 * b.z; acc[1][3] += a1 * b.w;
            acc[2][0] += a2 * b.x; acc[2][1] += a2 * b.y; acc[2][2] += a2 * b.z; acc[2][3] += a2 * b.w;
            acc[3][0] += a3 * b.x; acc[3][1] += a3 * b.y; acc[3][2] += a3 * b.z; acc[3][3] += a3 * b.w;
        }
    }

    float4 bias4 = *(const float4*)(bias + col0 + tx * 4);
#pragma unroll
    for (int i = 0; i < 4; i++) {
        int m = row0 + ty * 4 + i;
        int b_ = m / S;
        int s_ = m - b_ * S;
        float4 o;
        o.x = (acc[i][0] + bias4.x) * scale;
        o.y = (acc[i][1] + bias4.y) * scale;
        o.z = (acc[i][2] + bias4.z) * scale;
        o.w = (acc[i][3] + bias4.w) * scale;
        float* dst;
        if (HEAD) {
            dst = Y + (((size_t)(b_ * NH + blockIdx.x) * S + s_) * HD + tx * 4);
        } else {
            dst = Y + ((size_t)m * DM + col0 + tx * 4);
        }
        *(float4*)dst = o;
    }
}

#define ATTN_SMEM_FLOATS (64 * 64 + 3 * 64 * 65 + 64)
#define ATTN_SMEM_BYTES (ATTN_SMEM_FLOATS * 4)

// Flash attention, fp32. One CTA = (b, h, 64-row query tile).
__global__ __launch_bounds__(256)
void attn_kernel(const int* __restrict__ mask, float* __restrict__ O)
{
    extern __shared__ float sm[];
    float* Vs = sm;                 // [64][64]
    float* Qs = Vs + 64 * 64;       // [64][65]
    float* Ks = Qs + 64 * 65;       // [64][65]
    float* Ps = Ks + 64 * 65;       // [64][65]
    float* mk = Ps + 64 * 65;       // [64], 1.0 = masked

    const int tid = threadIdx.x;
    const int tx = tid & 15;
    const int ty = tid >> 4;
    const int b = blockIdx.z;
    const int h = blockIdx.y;
    const int q0 = blockIdx.x * 64;
    const int bh = b * NH + h;

    const float* Qg = g_Q + ((size_t)bh * NQ + q0) * HD;
    const float* Kg = g_K + (size_t)bh * LL * HD;
    const float* Vg = g_V + (size_t)bh * LL * HD;

    const int mbyte = g_mask_is_byte;
    const unsigned char* mask8 = (const unsigned char*)mask;

#pragma unroll
    for (int it = 0; it < 4; it++) {
        int lin = tid + it * 256;
        int r = lin >> 4;
        int c = (lin & 15) << 2;
        float4 v = *(const float4*)(Qg + r * HD + c);
        Qs[r * 65 + c + 0] = v.x;
        Qs[r * 65 + c + 1] = v.y;
        Qs[r * 65 + c + 2] = v.z;
        Qs[r * 65 + c + 3] = v.w;
    }

    float m_i[4], l_i[4], acc[4][4];
#pragma unroll
    for (int i = 0; i < 4; i++) {
        m_i[i] = -1e30f;
        l_i[i] = 0.0f;
#pragma unroll
        for (int j = 0; j < 4; j++) acc[i][j] = 0.0f;
    }

    for (int j0 = 0; j0 < LL; j0 += 64) {
        __syncthreads();
#pragma unroll
        for (int it = 0; it < 4; it++) {
            int lin = tid + it * 256;
            int r = lin >> 4;
            int c = (lin & 15) << 2;
            float4 kv = *(const float4*)(Kg + (size_t)(j0 + r) * HD + c);
            Ks[r * 65 + c + 0] = kv.x;
            Ks[r * 65 + c + 1] = kv.y;
            Ks[r * 65 + c + 2] = kv.z;
            Ks[r * 65 + c + 3] = kv.w;
            float4 vv = *(const float4*)(Vg + (size_t)(j0 + r) * HD + c);
            *(float4*)&Vs[r * 64 + c] = vv;
        }
        if (tid < 64) {
            int key = j0 + tid;
            int mval = mbyte ? (int)mask8[b * LL + key] : mask[b * LL + key];
            mk[tid] = (mval != 0) ? 1.0f : 0.0f;
        }
        __syncthreads();

        float s[4][4];
#pragma unroll
        for (int i = 0; i < 4; i++)
#pragma unroll
            for (int j = 0; j < 4; j++) s[i][j] = 0.0f;

#pragma unroll 8
        for (int d = 0; d < HD; d++) {
            float a0 = Qs[(ty * 4 + 0) * 65 + d];
            float a1 = Qs[(ty * 4 + 1) * 65 + d];
            float a2 = Qs[(ty * 4 + 2) * 65 + d];
            float a3 = Qs[(ty * 4 + 3) * 65 + d];
            float b0 = Ks[(tx * 4 + 0) * 65 + d];
            float b1 = Ks[(tx * 4 + 1) * 65 + d];
            float b2 = Ks[(tx * 4 + 2) * 65 + d];
            float b3 = Ks[(tx * 4 + 3) * 65 + d];
            s[0][0] += a0 * b0; s[0][1] += a0 * b1; s[0][2] += a0 * b2; s[0][3] += a0 * b3;
            s[1][0] += a1 * b0; s[1][1] += a1 * b1; s[1][2] += a1 * b2; s[1][3] += a1 * b3;
            s[2][0] += a2 * b0; s[2][1] += a2 * b1; s[2][2] += a2 * b2; s[2][3] += a2 * b3;
            s[3][0] += a3 * b0; s[3][1] += a3 * b1; s[3][2] += a3 * b2; s[3][3] += a3 * b3;
        }

        float kmf[4];
#pragma unroll
        for (int j = 0; j < 4; j++) kmf[j] = mk[tx * 4 + j];

#pragma unroll
        for (int i = 0; i < 4; i++) {
            float rmax = -1e30f;
#pragma unroll
            for (int j = 0; j < 4; j++)
                if (kmf[j] == 0.0f) rmax = fmaxf(rmax, s[i][j]);
#pragma unroll
            for (int off = 8; off >= 1; off >>= 1)
                rmax = fmaxf(rmax, __shfl_xor_sync(0xffffffffu, rmax, off));
            float newm = fmaxf(m_i[i], rmax);
            float alpha = __expf(m_i[i] - newm);
            m_i[i] = newm;
            float psum = 0.0f;
#pragma unroll
            for (int j = 0; j < 4; j++) {
                float p = (kmf[j] != 0.0f) ? 0.0f : __expf(s[i][j] - newm);
                s[i][j] = p;
                psum += p;
            }
#pragma unroll
            for (int off = 8; off >= 1; off >>= 1)
                psum += __shfl_xor_sync(0xffffffffu, psum, off);
            l_i[i] = l_i[i] * alpha + psum;
#pragma unroll
            for (int j = 0; j < 4; j++) {
                acc[i][j] *= alpha;
                Ps[(ty * 4 + i) * 65 + tx * 4 + j] = s[i][j];
            }
        }
        __syncthreads();

#pragma unroll 8
        for (int kk = 0; kk < 64; kk++) {
            float p0 = Ps[(ty * 4 + 0) * 65 + kk];
            float p1 = Ps[(ty * 4 + 1) * 65 + kk];
            float p2 = Ps[(ty * 4 + 2) * 65 + kk];
            float p3 = Ps[(ty * 4 + 3) * 65 + kk];
            float4 v = *(const float4*)&Vs[kk * 64 + tx * 4];
            acc[0][0] += p0 * v.x; acc[0][1] += p0 * v.y; acc[0][2] += p0 * v.z; acc[0][3] += p0 * v.w;
            acc[1][0] += p1 * v.x; acc[1][1] += p1 * v.y; acc[1][2] += p1 * v.z; acc[1][3] += p1 * v.w;
            acc[2][0] += p2 * v.x; acc[2][1] += p2 * v.y; acc[2][2] += p2 * v.z; acc[2][3] += p2 * v.w;
            acc[3][0] += p3 * v.x; acc[3][1] += p3 * v.y; acc[3][2] += p3 * v.z; acc[3][3] += p3 * v.w;
        }
    }

#pragma unroll
    for (int i = 0; i < 4; i++) {
        float rl = (l_i[i] > 0.0f) ? (1.0f / l_i[i]) : 0.0f;
        int q = q0 + ty * 4 + i;
        float4 o;
        o.x = acc[i][0] * rl;
        o.y = acc[i][1] * rl;
        o.z = acc[i][2] * rl;
        o.w = acc[i][3] * rl;
        *(float4*)(O + ((size_t)(b * NQ + q) * DM + h * HD + tx * 4)) = o;
    }
}

extern "C" void kernel_launch(void* const* d_in, const int* in_sizes, int n_in,
                              void* d_out, int out_size)
{
    const float* x_q  = (const float*)d_in[0];
    const float* x_kv = (const float*)d_in[1];
    const int*   mask = (const int*)d_in[2];
    const float* wq   = (const float*)d_in[3];
    const float* bq   = (const float*)d_in[4];
    const float* wk   = (const float*)d_in[5];
    const float* bk   = (const float*)d_in[6];
    const float* wv   = (const float*)d_in[7];
    const float* bv   = (const float*)d_in[8];
    const float* wo   = (const float*)d_in[9];
    const float* bo   = (const float*)d_in[10];
    float* out = (float*)d_out;

    float *pQ, *pK, *pV, *pAo;
    cudaGetSymbolAddress((void**)&pQ, g_Q);
    cudaGetSymbolAddress((void**)&pK, g_K);
    cudaGetSymbolAddress((void**)&pV, g_V);
    cudaGetSymbolAddress((void**)&pAo, g_Ao);

    cudaFuncSetAttribute(attn_kernel, cudaFuncAttributeMaxDynamicSharedMemorySize,
                         ATTN_SMEM_BYTES);

    detect_mask_kernel<<<1, 32>>>((const unsigned int*)mask);

    dim3 blk(256);
    dim3 gp(DM / 64, (BB * NQ) / 64);   // 16 x 64
    const float scale = 0.125f;          // 64^-0.5

    proj_kernel<true><<<gp, blk>>>(x_q, wq, bq, pQ, NQ, scale);
    proj_kernel<true><<<gp, blk>>>(x_kv, wk, bk, pK, LL, 1.0f);
    proj_kernel<true><<<gp, blk>>>(x_kv, wv, bv, pV, LL, 1.0f);

    dim3 ga(NQ / 64, NH, BB);            // 32 x 16 x 2
    attn_kernel<<<ga, blk, ATTN_SMEM_BYTES>>>(mask, pAo);

    proj_kernel<false><<<gp, blk>>>(pAo, wo, bo, out, NQ, 1.0f);
}

// round 4
// speedup vs baseline: 2.2553x; 2.2553x over previous
#include <cuda_runtime.h>
#include <cstdint>

#define BB 2
#define NQ 2048
#define LL 2048
#define DM 1024
#define NH 16
#define HD 64

// ---------------------------------------------------------------------------
// Scratch (allocation-free rule: __device__ globals)
// ---------------------------------------------------------------------------
__device__ float g_Q[BB * NH * NQ * HD];    // [B,H,N,HD], pre-scaled
__device__ float g_K[BB * NH * LL * HD];    // [B,H,L,HD]
__device__ float g_Vt[BB * NH * HD * LL];   // [B,H,HD,L]  (TRANSPOSED V)
__device__ float g_Ao[BB * NQ * DM];        // attention output, [B,N,D]
__device__ int   g_mask_is_byte;

// ---------------------------------------------------------------------------
// Helpers
// ---------------------------------------------------------------------------
__device__ __forceinline__ uint32_t cvt_tf32(float x) {
    uint32_t r;
    asm("cvt.rna.tf32.f32 %0, %1;" : "=r"(r) : "f"(x));
    return r;
}
__device__ __forceinline__ float tf(float x) { return __uint_as_float(cvt_tf32(x)); }
__device__ __forceinline__ float4 tf4(float4 v) {
    float4 o; o.x = tf(v.x); o.y = tf(v.y); o.z = tf(v.z); o.w = tf(v.w); return o;
}
#define F2U(x) __float_as_uint(x)

// m16n8k8 tf32 mma: D += A(row-major 16x8) * B(col-major 8x8)
__device__ __forceinline__ void mma8(float* c, const uint32_t* a, const uint32_t* b) {
    asm volatile(
        "mma.sync.aligned.m16n8k8.row.col.f32.tf32.tf32.f32 "
        "{%0,%1,%2,%3}, {%4,%5,%6,%7}, {%8,%9}, {%0,%1,%2,%3};"
        : "+f"(c[0]), "+f"(c[1]), "+f"(c[2]), "+f"(c[3])
        : "r"(a[0]), "r"(a[1]), "r"(a[2]), "r"(a[3]), "r"(b[0]), "r"(b[1]));
}

// exp(x) for x <= 0 on the FMA pipe. ~4e-5 max rel err.
__device__ __forceinline__ float fexp(float x) {
    float t = fmaxf(x * 1.4426950408889634f, -125.0f);
    float ff = t + 12582912.0f;
    int n = __float_as_int(ff) - 0x4B400000;
    float f = t - (ff - 12582912.0f);
    float p = 0.00961813f;
    p = fmaf(p, f, 0.0555041f);
    p = fmaf(p, f, 0.240227f);
    p = fmaf(p, f, 0.693147f);
    p = fmaf(p, f, 1.0f);
    return __int_as_float((n + 127) << 23) * p;
}

__global__ void detect_mask_kernel(const unsigned int* __restrict__ mask_words) {
    if (threadIdx.x == 0 && blockIdx.x == 0) {
        int flag = 0;
        for (int i = 0; i < 1024; i++) {
            if (mask_words[i] & ~1u) { flag = 1; break; }
        }
        g_mask_is_byte = flag;
    }
}

// ---------------------------------------------------------------------------
// mma.sync tf32 projection GEMM.  Y = (X @ W + bias) * scale
// CTA tile 128(M) x 64(N), 8 warps (4 m-groups x 2 n-groups), warp tile 32x32.
// MODE 0: Y flat [B*S, DM]
// MODE 1: Y as [B, H, S, HD]   (head == blockIdx.x since Ntile == HD)
// MODE 2: Y as [B, H, HD, S]   (transposed per head — for V)
// ---------------------------------------------------------------------------
#define PSA 36   // SMEM row stride (words); 36 % 32 == 4 -> conflict-free frag loads

template <int MODE>
__global__ __launch_bounds__(256)
void proj_mma(const float* __restrict__ X, const float* __restrict__ W,
              const float* __restrict__ bias, float* __restrict__ Y,
              int S, float scale)
{
    __shared__ float Xs[128 * PSA];   // [m][k] tf32
    __shared__ float Ws[64 * PSA];    // [n][k] tf32 (W^T tile)

    const int tid  = threadIdx.x;
    const int lane = tid & 31;
    const int wid  = tid >> 5;
    const int g    = lane >> 2;
    const int tg   = lane & 3;
    const int wm   = wid >> 1;       // 0..3
    const int wn   = wid & 1;        // 0..1
    const int row0 = blockIdx.y * 128;
    const int col0 = blockIdx.x * 64;

    // global load mapping
    const int xr  = tid >> 1;            // 0..127
    const int xc0 = (tid & 1) * 16;      // 0 or 16
    const int wnn = tid & 63;            // 0..63 (n)
    const int kg  = tid >> 6;            // 0..3 (k-group of 8)
    const float* Xp = X + (size_t)(row0 + xr) * DM + xc0;
    const float* Wp = W + col0 + wnn;

    float acc[2][4][4];
#pragma unroll
    for (int ma = 0; ma < 2; ma++)
#pragma unroll
        for (int na = 0; na < 4; na++)
#pragma unroll
            for (int i = 0; i < 4; i++) acc[ma][na][i] = 0.0f;

    float4 xa[4];
    float wb[8];
#pragma unroll
    for (int i = 0; i < 4; i++) xa[i] = *(const float4*)(Xp + i * 4);
#pragma unroll
    for (int i = 0; i < 8; i++) wb[i] = Wp[(size_t)(kg * 8 + i) * DM];

    for (int ch = 0; ch < 32; ch++) {
        __syncthreads();
        // stage current chunk (cvt to tf32)
#pragma unroll
        for (int i = 0; i < 4; i++)
            *(float4*)&Xs[xr * PSA + xc0 + i * 4] = tf4(xa[i]);
        {
            float4 o0, o1;
            o0.x = tf(wb[0]); o0.y = tf(wb[1]); o0.z = tf(wb[2]); o0.w = tf(wb[3]);
            o1.x = tf(wb[4]); o1.y = tf(wb[5]); o1.z = tf(wb[6]); o1.w = tf(wb[7]);
            *(float4*)&Ws[wnn * PSA + kg * 8 + 0] = o0;
            *(float4*)&Ws[wnn * PSA + kg * 8 + 4] = o1;
        }
        __syncthreads();
        // prefetch next chunk
        if (ch < 31) {
            const float* xp2 = Xp + (ch + 1) * 32;
#pragma unroll
            for (int i = 0; i < 4; i++) xa[i] = *(const float4*)(xp2 + i * 4);
#pragma unroll
            for (int i = 0; i < 8; i++)
                wb[i] = Wp[(size_t)((ch + 1) * 32 + kg * 8 + i) * DM];
        }
        // compute 4 k8-steps
#pragma unroll
        for (int ks = 0; ks < 4; ks++) {
            const int kc = ks * 8;
            uint32_t a[2][4], bfr[4][2];
#pragma unroll
            for (int ma = 0; ma < 2; ma++) {
                int r = wm * 32 + ma * 16 + g;
                a[ma][0] = F2U(Xs[r * PSA + kc + tg]);
                a[ma][1] = F2U(Xs[(r + 8) * PSA + kc + tg]);
                a[ma][2] = F2U(Xs[r * PSA + kc + tg + 4]);
                a[ma][3] = F2U(Xs[(r + 8) * PSA + kc + tg + 4]);
            }
#pragma unroll
            for (int na = 0; na < 4; na++) {
                int n = wn * 32 + na * 8 + g;
                bfr[na][0] = F2U(Ws[n * PSA + kc + tg]);
                bfr[na][1] = F2U(Ws[n * PSA + kc + tg + 4]);
            }
#pragma unroll
            for (int ma = 0; ma < 2; ma++)
#pragma unroll
                for (int na = 0; na < 4; na++)
                    mma8(acc[ma][na], a[ma], bfr[na]);
        }
    }

    // epilogue
#pragma unroll
    for (int ma = 0; ma < 2; ma++) {
#pragma unroll
        for (int na = 0; na < 4; na++) {
            const int colL = wn * 32 + na * 8 + 2 * tg;
            float2 bs = *(const float2*)(bias + col0 + colL);
#pragma unroll
            for (int rr = 0; rr < 2; rr++) {
                int m = row0 + wm * 32 + ma * 16 + g + rr * 8;
                int b_ = m / S;
                int s_ = m - b_ * S;
                float v0 = (acc[ma][na][rr * 2 + 0] + bs.x) * scale;
                float v1 = (acc[ma][na][rr * 2 + 1] + bs.y) * scale;
                if (MODE == 0) {
                    *(float2*)(Y + (size_t)m * DM + col0 + colL) = make_float2(v0, v1);
                } else if (MODE == 1) {
                    *(float2*)(Y + ((size_t)(b_ * NH + blockIdx.x) * S + s_) * HD + colL)
                        = make_float2(v0, v1);
                } else {
                    float* base = Y + ((size_t)(b_ * NH + blockIdx.x) * HD + colL) * LL + s_;
                    base[0]  = v0;
                    base[LL] = v1;
                }
            }
        }
    }
}

// ---------------------------------------------------------------------------
// Flash attention with mma.sync tf32. CTA = (b, h, 64-row q tile), 8 warps.
// Warp (wm, wk): rows [wm*16, +16); S-cols / O-cols [wk*32, +32).
// ---------------------------------------------------------------------------
#define ASA 68   // SMEM row stride; 68 % 32 == 4 -> conflict-free frag loads
#define ATTN_FLOATS (4 * 64 * ASA + 64 + 256)
#define ATTN_BYTES  (ATTN_FLOATS * 4)

__global__ __launch_bounds__(256)
void attn_mma(const int* __restrict__ mask, float* __restrict__ O)
{
    extern __shared__ float sm[];
    float* Qs   = sm;                    // [64][ASA] tf32
    float* Ks   = Qs + 64 * ASA;         // [64][ASA] tf32
    float* Vt   = Ks + 64 * ASA;         // [64(d)][ASA] tf32 (from g_Vt, no transpose)
    float* Ps   = Vt + 64 * ASA;         // [64][ASA] tf32
    float* mk   = Ps + 64 * ASA;         // [64]
    float* redm = mk + 64;               // [2][64]
    float* reds = redm + 128;            // [2][64]

    const int tid  = threadIdx.x;
    const int lane = tid & 31;
    const int wid  = tid >> 5;
    const int g    = lane >> 2;
    const int tg   = lane & 3;
    const int wm   = wid >> 1;           // 0..3
    const int wk   = wid & 1;            // 0..1
    const int b  = blockIdx.z;
    const int h  = blockIdx.y;
    const int q0 = blockIdx.x * 64;
    const int bh = b * NH + h;

    const float* Qg = g_Q  + ((size_t)bh * NQ + q0) * HD;
    const float* Kg = g_K  + (size_t)bh * LL * HD;
    const float* Vg = g_Vt + (size_t)bh * HD * LL;

    const int mbyte = g_mask_is_byte;
    const unsigned char* mask8 = (const unsigned char*)mask;

    // load Q tile
#pragma unroll
    for (int it = 0; it < 4; it++) {
        int lin = tid + it * 256;
        int r = lin >> 4;
        int c = (lin & 15) * 4;
        *(float4*)&Qs[r * ASA + c] = tf4(*(const float4*)(Qg + r * HD + c));
    }

    float m_i[2] = {-1e30f, -1e30f};
    float l_i[2] = {0.0f, 0.0f};
    float oacc[4][4];
#pragma unroll
    for (int na = 0; na < 4; na++)
#pragma unroll
        for (int i = 0; i < 4; i++) oacc[na][i] = 0.0f;

    for (int j0 = 0; j0 < LL; j0 += 64) {
        __syncthreads();
        // load K tile [key][d] and V tile [d][key] (already transposed in gmem)
#pragma unroll
        for (int it = 0; it < 4; it++) {
            int lin = tid + it * 256;
            int r = lin >> 4;
            int c = (lin & 15) * 4;
            *(float4*)&Ks[r * ASA + c] = tf4(*(const float4*)(Kg + (size_t)(j0 + r) * HD + c));
            *(float4*)&Vt[r * ASA + c] = tf4(*(const float4*)(Vg + (size_t)r * LL + j0 + c));
        }
        if (tid < 64) {
            int key = j0 + tid;
            int mval = mbyte ? (int)mask8[b * LL + key] : mask[b * LL + key];
            mk[tid] = (mval != 0) ? 1.0f : 0.0f;
        }
        __syncthreads();

        // ---- S = Q @ K^T  (warp: m16 x n32, k = 64)
        float sc[4][4];
#pragma unroll
        for (int na = 0; na < 4; na++)
#pragma unroll
            for (int i = 0; i < 4; i++) sc[na][i] = 0.0f;

#pragma unroll
        for (int ks = 0; ks < 8; ks++) {
            const int kc = ks * 8;
            uint32_t a[4];
            const int r = wm * 16 + g;
            a[0] = F2U(Qs[r * ASA + kc + tg]);
            a[1] = F2U(Qs[(r + 8) * ASA + kc + tg]);
            a[2] = F2U(Qs[r * ASA + kc + tg + 4]);
            a[3] = F2U(Qs[(r + 8) * ASA + kc + tg + 4]);
#pragma unroll
            for (int na = 0; na < 4; na++) {
                const int n = wk * 32 + na * 8 + g;
                uint32_t bfr[2] = { F2U(Ks[n * ASA + kc + tg]),
                                    F2U(Ks[n * ASA + kc + tg + 4]) };
                mma8(sc[na], a, bfr);
            }
        }

        // per-thread column masks (cols: wk*32 + na*8 + 2tg, +1)
        float km[4][2];
#pragma unroll
        for (int na = 0; na < 4; na++) {
            int c = wk * 32 + na * 8 + 2 * tg;
            km[na][0] = mk[c];
            km[na][1] = mk[c + 1];
        }

        // ---- row max over warp's 32 cols
        float rmax[2];
#pragma unroll
        for (int rr = 0; rr < 2; rr++) {
            rmax[rr] = -1e30f;
#pragma unroll
            for (int na = 0; na < 4; na++) {
                if (km[na][0] == 0.0f) rmax[rr] = fmaxf(rmax[rr], sc[na][rr * 2 + 0]);
                if (km[na][1] == 0.0f) rmax[rr] = fmaxf(rmax[rr], sc[na][rr * 2 + 1]);
            }
            rmax[rr] = fmaxf(rmax[rr], __shfl_xor_sync(0xffffffffu, rmax[rr], 1));
            rmax[rr] = fmaxf(rmax[rr], __shfl_xor_sync(0xffffffffu, rmax[rr], 2));
        }
        if (tg == 0) {
            redm[wk * 64 + wm * 16 + g]     = rmax[0];
            redm[wk * 64 + wm * 16 + g + 8] = rmax[1];
        }
        __syncthreads();

        // ---- online softmax update + P store
#pragma unroll
        for (int rr = 0; rr < 2; rr++) {
            const int row = wm * 16 + g + rr * 8;
            float rm = fmaxf(redm[row], redm[64 + row]);
            float newm = fmaxf(m_i[rr], rm);
            float alpha = fexp(m_i[rr] - newm);
            m_i[rr] = newm;
            float ps = 0.0f;
#pragma unroll
            for (int na = 0; na < 4; na++) {
                float p0 = (km[na][0] != 0.0f) ? 0.0f : fexp(sc[na][rr * 2 + 0] - newm);
                float p1 = (km[na][1] != 0.0f) ? 0.0f : fexp(sc[na][rr * 2 + 1] - newm);
                sc[na][rr * 2 + 0] = p0;
                sc[na][rr * 2 + 1] = p1;
                ps += p0 + p1;
            }
            ps += __shfl_xor_sync(0xffffffffu, ps, 1);
            ps += __shfl_xor_sync(0xffffffffu, ps, 2);
            if (tg == 0) reds[wk * 64 + row] = ps;
            l_i[rr] *= alpha;
#pragma unroll
            for (int na = 0; na < 4; na++) {
                oacc[na][rr * 2 + 0] *= alpha;
                oacc[na][rr * 2 + 1] *= alpha;
                int c = wk * 32 + na * 8 + 2 * tg;
                float2 pv;
                pv.x = __uint_as_float(cvt_tf32(sc[na][rr * 2 + 0]));
                pv.y = __uint_as_float(cvt_tf32(sc[na][rr * 2 + 1]));
                *(float2*)&Ps[row * ASA + c] = pv;
            }
        }
        __syncthreads();
#pragma unroll
        for (int rr = 0; rr < 2; rr++) {
            const int row = wm * 16 + g + rr * 8;
            l_i[rr] += reds[row] + reds[64 + row];
        }

        // ---- O += P @ V  (A = Ps rows, B = Vt[d][key])
#pragma unroll
        for (int ks = 0; ks < 8; ks++) {
            const int kc = ks * 8;
            uint32_t a[4];
            const int r = wm * 16 + g;
            a[0] = F2U(Ps[r * ASA + kc + tg]);
            a[1] = F2U(Ps[(r + 8) * ASA + kc + tg]);
            a[2] = F2U(Ps[r * ASA + kc + tg + 4]);
            a[3] = F2U(Ps[(r + 8) * ASA + kc + tg + 4]);
#pragma unroll
            for (int na = 0; na < 4; na++) {
                const int n = wk * 32 + na * 8 + g;
                uint32_t bfr[2] = { F2U(Vt[n * ASA + kc + tg]),
                                    F2U(Vt[n * ASA + kc + tg + 4]) };
                mma8(oacc[na], a, bfr);
            }
        }
    }

    // epilogue: normalize, write [B,N,D]
#pragma unroll
    for (int rr = 0; rr < 2; rr++) {
        float rl = (l_i[rr] > 0.0f) ? (1.0f / l_i[rr]) : 0.0f;
        int q = q0 + wm * 16 + g + rr * 8;
#pragma unroll
        for (int na = 0; na < 4; na++) {
            int c = h * HD + wk * 32 + na * 8 + 2 * tg;
            float2 o;
            o.x = oacc[na][rr * 2 + 0] * rl;
            o.y = oacc[na][rr * 2 + 1] * rl;
            *(float2*)(O + (size_t)(b * NQ + q) * DM + c) = o;
        }
    }
}

// ---------------------------------------------------------------------------
extern "C" void kernel_launch(void* const* d_in, const int* in_sizes, int n_in,
                              void* d_out, int out_size)
{
    const float* x_q  = (const float*)d_in[0];
    const float* x_kv = (const float*)d_in[1];
    const int*   mask = (const int*)d_in[2];
    const float* wq   = (const float*)d_in[3];
    const float* bq   = (const float*)d_in[4];
    const float* wk   = (const float*)d_in[5];
    const float* bk   = (const float*)d_in[6];
    const float* wv   = (const float*)d_in[7];
    const float* bv   = (const float*)d_in[8];
    const float* wo   = (const float*)d_in[9];
    const float* bo   = (const float*)d_in[10];
    float* out = (float*)d_out;

    float *pQ, *pK, *pVt, *pAo;
    cudaGetSymbolAddress((void**)&pQ, g_Q);
    cudaGetSymbolAddress((void**)&pK, g_K);
    cudaGetSymbolAddress((void**)&pVt, g_Vt);
    cudaGetSymbolAddress((void**)&pAo, g_Ao);

    cudaFuncSetAttribute(attn_mma, cudaFuncAttributeMaxDynamicSharedMemorySize,
                         ATTN_BYTES);

    detect_mask_kernel<<<1, 32>>>((const unsigned int*)mask);

    dim3 blk(256);
    dim3 gp(DM / 64, (BB * NQ) / 128);   // 16 x 32
    const float scale = 0.125f;          // 64^-0.5

    proj_mma<1><<<gp, blk>>>(x_q,  wq, bq, pQ,  NQ, scale);
    proj_mma<1><<<gp, blk>>>(x_kv, wk, bk, pK,  LL, 1.0f);
    proj_mma<2><<<gp, blk>>>(x_kv, wv, bv, pVt, LL, 1.0f);

    dim3 ga(NQ / 64, NH, BB);            // 32 x 16 x 2
    attn_mma<<<ga, blk, ATTN_BYTES>>>(mask, pAo);

    proj_mma<0><<<gp, blk>>>(pAo, wo, bo, out, NQ, 1.0f);
}